// round 15
// baseline (speedup 1.0000x reference)
#include <cuda_runtime.h>
#include <cuda_bf16.h>
#include <mma.h>
#include <math.h>

using namespace nvcuda;

#define B_    64
#define P_    196
#define ENC_  512
#define EMB_  256
#define ATT_  256
#define DEC_  256
#define V_    10000
#define T_    44
#define NG_   1024           // 4*DEC
#define KX2_  768            // ENC + DEC (emb part hoisted out of loop)
#define SPLITK_ 12           // gates GEMM K chunks of 64 (192 parallel blocks)

// ---------------- device scratch (static: no allocation allowed) ----------------
__device__ float g_att1[B_ * P_ * ATT_];        // encoder attention keys
__device__ float g_WdaT[ATT_ * DEC_];           // W_dec_att transposed [k][j]
__device__ float g_Wcat2[NG_ * KX2_];           // [W_ih[:, :512] | W_hh] row-major [j][k]
__device__ float g_embx[T_ * B_ * EMB_];        // gathered embeddings, all steps
__device__ float g_Wemb[NG_ * EMB_];            // W_ih[:, 512:768]
__device__ float g_gemb[T_ * B_ * NG_];         // precomputed emb gate contributions
__device__ float g_h0[B_ * DEC_];
__device__ float g_c[2][B_ * DEC_];             // parity double-buffered cell state
__device__ float g_x[B_ * KX2_];                // per-step LSTM input [ctx | h]
__device__ float g_gpart[SPLITK_ * B_ * NG_];   // split-K gate partials

// bf16 hi/lo split operands for tensor GEMMs
__device__ __nv_bfloat16 g_encH[B_ * P_ * ENC_],  g_encL[B_ * P_ * ENC_];
__device__ __nv_bfloat16 g_weaH[ATT_ * ENC_],     g_weaL[ATT_ * ENC_];
__device__ __nv_bfloat16 g_embxH[T_ * B_ * EMB_], g_embxL[T_ * B_ * EMB_];
__device__ __nv_bfloat16 g_wembH[NG_ * EMB_],     g_wembL[NG_ * EMB_];
__device__ __nv_bfloat16 g_hallH[T_ * B_ * DEC_], g_hallL[T_ * B_ * DEC_];  // cell writes directly
__device__ __nv_bfloat16 g_woutH[V_ * DEC_],      g_woutL[V_ * DEC_];

__device__ __forceinline__ float sigm(float x) { return 1.0f / (1.0f + expf(-x)); }

// ---------------- fp32 -> bf16 hi/lo split ----------------
__global__ void k_cvt(const float* __restrict__ src, __nv_bfloat16* __restrict__ hi,
                      __nv_bfloat16* __restrict__ lo, int n) {
    int i = blockIdx.x * 256 + threadIdx.x;
    if (i < n) {
        float v = src[i];
        __nv_bfloat16 h = __float2bfloat16(v);
        hi[i] = h;
        lo[i] = __float2bfloat16(v - __bfloat162float(h));
    }
}

// ---------------- one-time weight prep (transpose / concat / gather) ----------------
__global__ void k_prep(const float* __restrict__ W_ih, const float* __restrict__ W_hh,
                       const float* __restrict__ W_dec_att,
                       const float* __restrict__ embedding, const int* __restrict__ caption) {
    int idx = blockIdx.x * blockDim.x + threadIdx.x;
    if (idx < NG_ * KX2_) {
        int j = idx / KX2_, k = idx % KX2_;
        g_Wcat2[idx] = (k < 512) ? W_ih[j * 768 + k] : W_hh[j * 256 + (k - 512)];
    }
    int i2 = idx - NG_ * KX2_;
    if (i2 >= 0 && i2 < ATT_ * DEC_) {
        int k = i2 >> 8, j = i2 & 255;
        g_WdaT[i2] = W_dec_att[j * 256 + k];
    }
    int i3 = i2 - ATT_ * DEC_;
    if (i3 >= 0 && i3 < NG_ * EMB_) {
        int j = i3 >> 8, k = i3 & 255;
        g_Wemb[i3] = W_ih[j * 768 + 512 + k];
    }
    int i4 = i3 - NG_ * EMB_;
    if (i4 >= 0 && i4 < T_ * B_ * EMB_) {
        int m = i4 >> 8, k = i4 & 255;
        int b = m & (B_ - 1), t = m >> 6;
        g_embx[i4] = embedding[(size_t)caption[b * T_ + t] * EMB_ + k];
    }
}

// ---------------- init h0/c0 from mean-pooled encoder ----------------
__global__ void k_init(const float* __restrict__ enc,
                       const float* __restrict__ W_init_h, const float* __restrict__ b_init_h,
                       const float* __restrict__ W_init_c, const float* __restrict__ b_init_c) {
    int b = blockIdx.x, tid = threadIdx.x;
    __shared__ float avg[ENC_];
    #pragma unroll
    for (int e0 = 0; e0 < 2; e0++) {
        int e = tid + e0 * 256;
        float s = 0.f;
        for (int p = 0; p < P_; p++) s += enc[((size_t)(b * P_ + p)) * ENC_ + e];
        avg[e] = s * (1.0f / (float)P_);
    }
    __syncthreads();
    float h = b_init_h[tid], c = b_init_c[tid];
    const float* wh = W_init_h + (size_t)tid * ENC_;
    const float* wc = W_init_c + (size_t)tid * ENC_;
    #pragma unroll 8
    for (int k = 0; k < ENC_; k++) { h += avg[k] * wh[k]; c += avg[k] * wc[k]; }
    g_h0[b * DEC_ + tid] = h;
    g_c[0][b * DEC_ + tid] = c;   // c_0 lives in parity buffer 0
}

// ========== bf16 hi/lo split WMMA GEMM (m16n16k16, fp32 acc; ~1e-5 accuracy) ==========
// C[m][n] = sum_k A[m][k]*B[n][k] (+bias) with A=Ah+Al, B=Bh+Bl; acc = AhBh+AhBl+AlBh.
// CTA 128x128, 8 warps (4m x 2n), warp tile 32x64. K-chunk 32, double-buffered,
// register prefetch. Tiles stored row-major [row][40] bf16 (ldm 40, mult of 8).
// PERM=1: row m encodes (t*B + b); store to C[(b*T + t)*V + n].
#define BT_LD 40
#define BT_TILE (128 * BT_LD)                 // elems per tile per stage
#define BGEMM_SMEM (8 * BT_TILE * 2 + 8 * 16 * 20 * 4)   // 81920 + 10240 bytes

template<int PERM>
__global__ __launch_bounds__(256) void bgemm(
        const __nv_bfloat16* __restrict__ Ah, const __nv_bfloat16* __restrict__ Al,
        const __nv_bfloat16* __restrict__ Bh, const __nv_bfloat16* __restrict__ Bl,
        const float* __restrict__ bias, float* __restrict__ C,
        int M, int N, int K) {
    extern __shared__ __align__(16) __nv_bfloat16 smb[];
    __nv_bfloat16* sAh = smb;                 // [2][BT_TILE]
    __nv_bfloat16* sAl = smb + 2 * BT_TILE;
    __nv_bfloat16* sBh = smb + 4 * BT_TILE;
    __nv_bfloat16* sBl = smb + 6 * BT_TILE;
    float* epi = (float*)(smb + 8 * BT_TILE); // [8][16][20]

    int tid = threadIdx.x;
    int wid = tid >> 5, lane = tid & 31;
    int wm = wid & 3, wn = wid >> 2;
    int m0 = blockIdx.x * 128, n0 = blockIdx.y * 128;
    int lrow = tid >> 2;           // 0..63
    int lk8 = (tid & 3) * 8;       // 0,8,16,24 (bf16 elems within 32-chunk)

    const __nv_bfloat16* ApH0 = Ah + (size_t)(m0 + lrow) * K + lk8;
    const __nv_bfloat16* ApH1 = Ah + (size_t)(m0 + lrow + 64) * K + lk8;
    const __nv_bfloat16* ApL0 = Al + (size_t)(m0 + lrow) * K + lk8;
    const __nv_bfloat16* ApL1 = Al + (size_t)(m0 + lrow + 64) * K + lk8;
    bool bok0 = (n0 + lrow) < N, bok1 = (n0 + lrow + 64) < N;
    size_t br0 = (size_t)(bok0 ? n0 + lrow : 0) * K + lk8;
    size_t br1 = (size_t)(bok1 ? n0 + lrow + 64 : 0) * K + lk8;
    const uint4 z4 = make_uint4(0u, 0u, 0u, 0u);

    int so0 = lrow * BT_LD + lk8;
    int so1 = (lrow + 64) * BT_LD + lk8;

    // prologue: chunk 0 -> stage 0
    {
        *(uint4*)(sAh + so0) = *(const uint4*)ApH0;
        *(uint4*)(sAh + so1) = *(const uint4*)ApH1;
        *(uint4*)(sAl + so0) = *(const uint4*)ApL0;
        *(uint4*)(sAl + so1) = *(const uint4*)ApL1;
        *(uint4*)(sBh + so0) = bok0 ? *(const uint4*)(Bh + br0) : z4;
        *(uint4*)(sBh + so1) = bok1 ? *(const uint4*)(Bh + br1) : z4;
        *(uint4*)(sBl + so0) = bok0 ? *(const uint4*)(Bl + br0) : z4;
        *(uint4*)(sBl + so1) = bok1 ? *(const uint4*)(Bl + br1) : z4;
    }
    __syncthreads();

    wmma::fragment<wmma::accumulator, 16, 16, 16, float> acc[2][4];
    #pragma unroll
    for (int mi = 0; mi < 2; mi++)
        #pragma unroll
        for (int ni = 0; ni < 4; ni++) wmma::fill_fragment(acc[mi][ni], 0.f);

    int buf = 0;
    for (int k0 = 32; k0 < K; k0 += 32) {
        uint4 rah0 = *(const uint4*)(ApH0 + k0);
        uint4 rah1 = *(const uint4*)(ApH1 + k0);
        uint4 ral0 = *(const uint4*)(ApL0 + k0);
        uint4 ral1 = *(const uint4*)(ApL1 + k0);
        uint4 rbh0 = bok0 ? *(const uint4*)(Bh + br0 + k0) : z4;
        uint4 rbh1 = bok1 ? *(const uint4*)(Bh + br1 + k0) : z4;
        uint4 rbl0 = bok0 ? *(const uint4*)(Bl + br0 + k0) : z4;
        uint4 rbl1 = bok1 ? *(const uint4*)(Bl + br1 + k0) : z4;

        const __nv_bfloat16* bAh = sAh + buf * BT_TILE;
        const __nv_bfloat16* bAl = sAl + buf * BT_TILE;
        const __nv_bfloat16* bBh = sBh + buf * BT_TILE;
        const __nv_bfloat16* bBl = sBl + buf * BT_TILE;
        #pragma unroll
        for (int ks = 0; ks < 2; ks++) {
            wmma::fragment<wmma::matrix_a, 16, 16, 16, __nv_bfloat16, wmma::row_major> ah[2], al[2];
            wmma::fragment<wmma::matrix_b, 16, 16, 16, __nv_bfloat16, wmma::col_major> bh[4], bl[4];
            #pragma unroll
            for (int mi = 0; mi < 2; mi++) {
                wmma::load_matrix_sync(ah[mi], bAh + (wm * 32 + mi * 16) * BT_LD + ks * 16, BT_LD);
                wmma::load_matrix_sync(al[mi], bAl + (wm * 32 + mi * 16) * BT_LD + ks * 16, BT_LD);
            }
            #pragma unroll
            for (int ni = 0; ni < 4; ni++) {
                wmma::load_matrix_sync(bh[ni], bBh + (wn * 64 + ni * 16) * BT_LD + ks * 16, BT_LD);
                wmma::load_matrix_sync(bl[ni], bBl + (wn * 64 + ni * 16) * BT_LD + ks * 16, BT_LD);
            }
            #pragma unroll
            for (int mi = 0; mi < 2; mi++)
                #pragma unroll
                for (int ni = 0; ni < 4; ni++) {
                    wmma::mma_sync(acc[mi][ni], ah[mi], bh[ni], acc[mi][ni]);
                    wmma::mma_sync(acc[mi][ni], ah[mi], bl[ni], acc[mi][ni]);
                    wmma::mma_sync(acc[mi][ni], al[mi], bh[ni], acc[mi][ni]);
                }
        }
        int nb = buf ^ 1;
        *(uint4*)(sAh + nb * BT_TILE + so0) = rah0;
        *(uint4*)(sAh + nb * BT_TILE + so1) = rah1;
        *(uint4*)(sAl + nb * BT_TILE + so0) = ral0;
        *(uint4*)(sAl + nb * BT_TILE + so1) = ral1;
        *(uint4*)(sBh + nb * BT_TILE + so0) = rbh0;
        *(uint4*)(sBh + nb * BT_TILE + so1) = rbh1;
        *(uint4*)(sBl + nb * BT_TILE + so0) = rbl0;
        *(uint4*)(sBl + nb * BT_TILE + so1) = rbl1;
        __syncthreads();
        buf = nb;
    }
    {
        const __nv_bfloat16* bAh = sAh + buf * BT_TILE;
        const __nv_bfloat16* bAl = sAl + buf * BT_TILE;
        const __nv_bfloat16* bBh = sBh + buf * BT_TILE;
        const __nv_bfloat16* bBl = sBl + buf * BT_TILE;
        #pragma unroll
        for (int ks = 0; ks < 2; ks++) {
            wmma::fragment<wmma::matrix_a, 16, 16, 16, __nv_bfloat16, wmma::row_major> ah[2], al[2];
            wmma::fragment<wmma::matrix_b, 16, 16, 16, __nv_bfloat16, wmma::col_major> bh[4], bl[4];
            #pragma unroll
            for (int mi = 0; mi < 2; mi++) {
                wmma::load_matrix_sync(ah[mi], bAh + (wm * 32 + mi * 16) * BT_LD + ks * 16, BT_LD);
                wmma::load_matrix_sync(al[mi], bAl + (wm * 32 + mi * 16) * BT_LD + ks * 16, BT_LD);
            }
            #pragma unroll
            for (int ni = 0; ni < 4; ni++) {
                wmma::load_matrix_sync(bh[ni], bBh + (wn * 64 + ni * 16) * BT_LD + ks * 16, BT_LD);
                wmma::load_matrix_sync(bl[ni], bBl + (wn * 64 + ni * 16) * BT_LD + ks * 16, BT_LD);
            }
            #pragma unroll
            for (int mi = 0; mi < 2; mi++)
                #pragma unroll
                for (int ni = 0; ni < 4; ni++) {
                    wmma::mma_sync(acc[mi][ni], ah[mi], bh[ni], acc[mi][ni]);
                    wmma::mma_sync(acc[mi][ni], ah[mi], bl[ni], acc[mi][ni]);
                    wmma::mma_sync(acc[mi][ni], al[mi], bh[ni], acc[mi][ni]);
                }
        }
    }

    float* myepi = epi + wid * 16 * 20;
    #pragma unroll
    for (int mi = 0; mi < 2; mi++) {
        #pragma unroll
        for (int ni = 0; ni < 4; ni++) {
            wmma::store_matrix_sync(myepi, acc[mi][ni], 20, wmma::mem_row_major);
            __syncwarp();
            int mbase = m0 + wm * 32 + mi * 16;
            int nbase = n0 + wn * 64 + ni * 16;
            int r = lane >> 1, c0 = (lane & 1) * 8;
            int m = mbase + r;
            size_t rowbase;
            if (PERM) {
                int b = m & (B_ - 1), t = m >> 6;
                rowbase = ((size_t)b * T_ + t) * (size_t)V_;
            } else {
                rowbase = (size_t)m * (size_t)N;
            }
            #pragma unroll
            for (int c = 0; c < 8; c++) {
                int n = nbase + c0 + c;
                if (n < N)
                    C[rowbase + n] = myepi[r * 20 + c0 + c] + (bias ? bias[n] : 0.f);
            }
            __syncwarp();
        }
    }
}

// ---------------- cell body: finishes step (t-1)'s LSTM cell ---------------------------
// Writes h directly as bf16 hi/lo (only the logits GEMM consumes hall).
__device__ __forceinline__ void cell_body(int t, int b, int tid,
                                          const float* __restrict__ b_ih,
                                          const float* __restrict__ b_hh,
                                          float* h_sh) {
    const float* ge = g_gemb + ((size_t)(t - 1) * B_ + b) * NG_;
    float gi = b_ih[tid]       + b_hh[tid]       + ge[tid];
    float gf = b_ih[tid + 256] + b_hh[tid + 256] + ge[tid + 256];
    float gg = b_ih[tid + 512] + b_hh[tid + 512] + ge[tid + 512];
    float go = b_ih[tid + 768] + b_hh[tid + 768] + ge[tid + 768];
    #pragma unroll
    for (int s = 0; s < SPLITK_; s++) {
        const float* gp = g_gpart + ((size_t)s * B_ + b) * NG_;
        gi += gp[tid]; gf += gp[tid + 256]; gg += gp[tid + 512]; go += gp[tid + 768];
    }
    float c  = g_c[(t - 1) & 1][b * DEC_ + tid];
    float cn = sigm(gf) * c + sigm(gi) * tanhf(gg);
    float hn = sigm(go) * tanhf(cn);
    g_c[t & 1][b * DEC_ + tid] = cn;
    size_t hidx = ((size_t)(t - 1) * B_ + b) * DEC_ + tid;
    __nv_bfloat16 hh = __float2bfloat16(hn);
    g_hallH[hidx] = hh;
    g_hallL[hidx] = __float2bfloat16(hn - __bfloat162float(hh));
    if (h_sh) h_sh[tid] = hn;
}

// ---------------- per-step kernel 1 (MERGED): cell + att2 + ALL scores + softmax + ctx -
// grid (B, 8). Each y-block redundantly computes cell, att2, all 196 scores, and the
// softmax (identical values, deterministic), then handles its own 64-e ctx chunk.
// y==0 additionally writes alphas and h into g_x. One launch-slot replaces two.
__global__ void k_att(int t, const float* __restrict__ enc, const float* __restrict__ Wfull,
                      const float* __restrict__ b_ih, const float* __restrict__ b_hh,
                      float* __restrict__ alphas_out) {
    int b = blockIdx.x, tid = threadIdx.x;
    int e0 = blockIdx.y * 64;
    __shared__ float h_sh[256], att2s[256], wfs[256], sc[256], red[256];

    // ---- finish previous step's LSTM cell (redundant 8x; identical writes) ----
    if (t > 0) cell_body(t, b, tid, b_ih, b_hh, h_sh);
    else       h_sh[tid] = g_h0[b * DEC_ + tid];
    if (blockIdx.y == 0) g_x[b * KX2_ + ENC_ + tid] = h_sh[tid];
    wfs[tid] = Wfull[tid];
    __syncthreads();

    // ---- att2[j] = h . W_dec_att[j,:]  (WdaT k-major -> coalesced) ----
    float a2 = 0.f;
    #pragma unroll 8
    for (int k = 0; k < 256; k++) a2 += h_sh[k] * g_WdaT[k * 256 + tid];
    att2s[tid] = a2;
    __syncthreads();

    // ---- all 196 scores: warp per p round-robin ----
    int lane = tid & 31, wid = tid >> 5;
    for (int p = wid; p < P_; p += 8) {
        const float* row = g_att1 + ((size_t)(b * P_ + p)) * ATT_;
        float s = 0.f;
        #pragma unroll
        for (int a = lane; a < 256; a += 32) {
            float v = row[a] + att2s[a];
            s += fmaxf(v, 0.f) * wfs[a];
        }
        #pragma unroll
        for (int o = 16; o > 0; o >>= 1) s += __shfl_down_sync(0xffffffffu, s, o);
        if (lane == 0) sc[p] = s;
    }
    __syncthreads();

    // ---- softmax over P=196 (deterministic; identical in all y-blocks) ----
    float sv = (tid < P_) ? sc[tid] : -1e30f;
    red[tid] = sv;
    __syncthreads();
    for (int s = 128; s > 0; s >>= 1) { if (tid < s) red[tid] = fmaxf(red[tid], red[tid + s]); __syncthreads(); }
    float mx = red[0];
    __syncthreads();
    float ex = (tid < P_) ? expf(sv - mx) : 0.f;
    red[tid] = ex;
    __syncthreads();
    for (int s = 128; s > 0; s >>= 1) { if (tid < s) red[tid] += red[tid + s]; __syncthreads(); }
    float alpha = ex * (1.0f / red[0]);
    __syncthreads();
    sc[tid] = alpha;
    if (blockIdx.y == 0 && tid < P_)
        alphas_out[((size_t)b * T_ + t) * P_ + tid] = alpha;
    __syncthreads();

    // ---- ctx chunk: 64 e's, 4 threads per e ----
    int e = tid & 63, ps = tid >> 6;
    float s = 0.f;
    for (int p = ps; p < P_; p += 4)
        s += sc[p] * enc[((size_t)(b * P_ + p)) * ENC_ + e0 + e];
    red[tid] = s;
    __syncthreads();
    if (tid < 64)
        g_x[b * KX2_ + e0 + tid] = red[tid] + red[tid + 64] + red[tid + 128] + red[tid + 192];
}

// ---------------- final cell only (after last step's gates) ----------------------------
__global__ void k_cell_final(const float* __restrict__ b_ih, const float* __restrict__ b_hh) {
    cell_body(T_, blockIdx.x, threadIdx.x, b_ih, b_hh, nullptr);
}

// ---------------- per-step kernel 2: gates GEMM, split-K over K=768 (12 x 64) ----------
__global__ void k_gates() {
    __shared__ float Xs[64][68];
    __shared__ float Ws[64][68];
    int tid = threadIdx.x;
    int j0 = blockIdx.x * 64;
    int k0 = blockIdx.y * 64;
    #pragma unroll
    for (int r = 0; r < 16; r++) {
        int row = r * 4 + (tid >> 6);
        int k = tid & 63;
        Xs[k][row] = g_x[(size_t)row * KX2_ + k0 + k];
        Ws[k][row] = g_Wcat2[(size_t)(j0 + row) * KX2_ + k0 + k];
    }
    __syncthreads();
    int tx = tid & 15, ty = tid >> 4;
    float acc[4][4] = {};
    #pragma unroll
    for (int kk = 0; kk < 64; kk++) {
        float4 xb = *(const float4*)&Xs[kk][ty * 4];
        float4 wj = *(const float4*)&Ws[kk][tx * 4];
        acc[0][0] += xb.x * wj.x; acc[0][1] += xb.x * wj.y; acc[0][2] += xb.x * wj.z; acc[0][3] += xb.x * wj.w;
        acc[1][0] += xb.y * wj.x; acc[1][1] += xb.y * wj.y; acc[1][2] += xb.y * wj.z; acc[1][3] += xb.y * wj.w;
        acc[2][0] += xb.z * wj.x; acc[2][1] += xb.z * wj.y; acc[2][2] += xb.z * wj.z; acc[2][3] += xb.z * wj.w;
        acc[3][0] += xb.w * wj.x; acc[3][1] += xb.w * wj.y; acc[3][2] += xb.w * wj.z; acc[3][3] += xb.w * wj.w;
    }
    #pragma unroll
    for (int bi = 0; bi < 4; bi++) {
        int b = ty * 4 + bi;
        #pragma unroll
        for (int ji = 0; ji < 4; ji++) {
            g_gpart[((size_t)blockIdx.y * B_ + b) * NG_ + j0 + tx * 4 + ji] = acc[bi][ji];
        }
    }
}

// ---------------- launch ----------------
extern "C" void kernel_launch(void* const* d_in, const int* in_sizes, int n_in,
                              void* d_out, int out_size) {
    const float* enc       = (const float*)d_in[0];
    const int*   caption   = (const int*)  d_in[1];
    const float* W_enc_att = (const float*)d_in[2];
    const float* W_dec_att = (const float*)d_in[3];
    const float* W_full    = (const float*)d_in[4];
    const float* embedding = (const float*)d_in[5];
    const float* W_init_h  = (const float*)d_in[6];
    const float* b_init_h  = (const float*)d_in[7];
    const float* W_init_c  = (const float*)d_in[8];
    const float* b_init_c  = (const float*)d_in[9];
    const float* W_ih      = (const float*)d_in[10];
    const float* b_ih      = (const float*)d_in[11];
    const float* W_hh      = (const float*)d_in[12];
    const float* b_hh      = (const float*)d_in[13];
    const float* W_out     = (const float*)d_in[14];
    const float* b_out     = (const float*)d_in[15];

    float* out    = (float*)d_out;
    float* preds  = out;                              // [B, T, V]
    float* alphas = out + (size_t)B_ * T_ * V_;       // [B, T, P]

    float *att1p, *embxp, *wembp, *gembp;
    cudaGetSymbolAddress((void**)&att1p, g_att1);
    cudaGetSymbolAddress((void**)&embxp, g_embx);
    cudaGetSymbolAddress((void**)&wembp, g_Wemb);
    cudaGetSymbolAddress((void**)&gembp, g_gemb);

    __nv_bfloat16 *encH, *encL, *weaH, *weaL, *embxH, *embxL, *wembH, *wembL,
                  *hallH, *hallL, *woutH, *woutL;
    cudaGetSymbolAddress((void**)&encH, g_encH);   cudaGetSymbolAddress((void**)&encL, g_encL);
    cudaGetSymbolAddress((void**)&weaH, g_weaH);   cudaGetSymbolAddress((void**)&weaL, g_weaL);
    cudaGetSymbolAddress((void**)&embxH, g_embxH); cudaGetSymbolAddress((void**)&embxL, g_embxL);
    cudaGetSymbolAddress((void**)&wembH, g_wembH); cudaGetSymbolAddress((void**)&wembL, g_wembL);
    cudaGetSymbolAddress((void**)&hallH, g_hallH); cudaGetSymbolAddress((void**)&hallL, g_hallL);
    cudaGetSymbolAddress((void**)&woutH, g_woutH); cudaGetSymbolAddress((void**)&woutL, g_woutL);

    cudaFuncSetAttribute(bgemm<0>, cudaFuncAttributeMaxDynamicSharedMemorySize, BGEMM_SMEM);
    cudaFuncSetAttribute(bgemm<1>, cudaFuncAttributeMaxDynamicSharedMemorySize, BGEMM_SMEM);

    // one-time prep
    int prep_total = NG_ * KX2_ + ATT_ * DEC_ + NG_ * EMB_ + T_ * B_ * EMB_;
    k_prep<<<(prep_total + 255) / 256, 256>>>(W_ih, W_hh, W_dec_att, embedding, caption);
    k_init<<<B_, 256>>>(enc, W_init_h, b_init_h, W_init_c, b_init_c);

    // bf16 hi/lo conversions for tensor GEMM operands
    k_cvt<<<(B_ * P_ * ENC_ + 255) / 256, 256>>>(enc, encH, encL, B_ * P_ * ENC_);
    k_cvt<<<(ATT_ * ENC_ + 255) / 256, 256>>>(W_enc_att, weaH, weaL, ATT_ * ENC_);
    k_cvt<<<(T_ * B_ * EMB_ + 255) / 256, 256>>>(embxp, embxH, embxL, T_ * B_ * EMB_);
    k_cvt<<<(NG_ * EMB_ + 255) / 256, 256>>>(wembp, wembH, wembL, NG_ * EMB_);
    k_cvt<<<(V_ * DEC_ + 255) / 256, 256>>>(W_out, woutH, woutL, V_ * DEC_);

    // att1[b,p,a] = enc[b,p,:] . W_enc_att[a,:]   (M=12544, N=256, K=512)  tensor
    bgemm<0><<<dim3(98, 2), 256, BGEMM_SMEM>>>(encH, encL, weaH, weaL, nullptr, att1p,
                                               B_ * P_, ATT_, ENC_);
    // gemb[t*B+b][j] = embx . Wemb^T               (M=2816, N=1024, K=256)  tensor
    bgemm<0><<<dim3(22, 8), 256, BGEMM_SMEM>>>(embxH, embxL, wembH, wembL, nullptr, gembp,
                                               T_ * B_, NG_, EMB_);

    // recurrence: 2 wide kernels per step (merged attention kernel + gates GEMM)
    for (int t = 0; t < T_; t++) {
        k_att<<<dim3(B_, 8), 256>>>(t, enc, W_full, b_ih, b_hh, alphas);
        k_gates<<<dim3(NG_ / 64, SPLITK_), 256>>>();
    }
    k_cell_final<<<B_, 256>>>(b_ih, b_hh);

    // batched logits (hall already bf16 hi/lo from the cell): -> [B, T, V]
    bgemm<1><<<dim3((T_ * B_) / 128, (V_ + 127) / 128), 256, BGEMM_SMEM>>>(
        hallH, hallL, woutH, woutL, b_out, preds, T_ * B_, V_, DEC_);
}

// round 16
// speedup vs baseline: 1.2580x; 1.2580x over previous
#include <cuda_runtime.h>
#include <cuda_bf16.h>
#include <mma.h>
#include <math.h>

using namespace nvcuda;

#define B_    64
#define P_    196
#define ENC_  512
#define EMB_  256
#define ATT_  256
#define DEC_  256
#define V_    10000
#define T_    44
#define NG_   1024           // 4*DEC
#define KX2_  768            // ENC + DEC (emb part hoisted out of loop)
#define SPLITK_ 12           // gates GEMM K chunks of 64 (192 parallel blocks)

// ---------------- device scratch (static: no allocation allowed) ----------------
__device__ float g_att1[B_ * P_ * ATT_];        // encoder attention keys
__device__ float g_WdaT[ATT_ * DEC_];           // W_dec_att transposed [k][j]
__device__ float g_Wcat2[NG_ * KX2_];           // [W_ih[:, :512] | W_hh] row-major [j][k]
__device__ float g_embx[T_ * B_ * EMB_];        // gathered embeddings, all steps
__device__ float g_Wemb[NG_ * EMB_];            // W_ih[:, 512:768]
__device__ float g_gemb[T_ * B_ * NG_];         // precomputed emb gate contributions
__device__ float g_h0[B_ * DEC_];
__device__ float g_c[2][B_ * DEC_];             // parity double-buffered cell state
__device__ float g_x[B_ * KX2_];                // per-step LSTM input [ctx | h]
__device__ float g_scores[B_ * P_];
__device__ float g_gpart[SPLITK_ * B_ * NG_];   // split-K gate partials

// bf16 hi/lo split operands for tensor GEMMs
__device__ __nv_bfloat16 g_encH[B_ * P_ * ENC_],  g_encL[B_ * P_ * ENC_];
__device__ __nv_bfloat16 g_weaH[ATT_ * ENC_],     g_weaL[ATT_ * ENC_];
__device__ __nv_bfloat16 g_embxH[T_ * B_ * EMB_], g_embxL[T_ * B_ * EMB_];
__device__ __nv_bfloat16 g_wembH[NG_ * EMB_],     g_wembL[NG_ * EMB_];
__device__ __nv_bfloat16 g_hallH[T_ * B_ * DEC_], g_hallL[T_ * B_ * DEC_];  // cell writes directly
__device__ __nv_bfloat16 g_woutH[V_ * DEC_],      g_woutL[V_ * DEC_];

__device__ __forceinline__ float sigm(float x) { return 1.0f / (1.0f + expf(-x)); }

// ---------------- fp32 -> bf16 hi/lo split ----------------
__global__ void k_cvt(const float* __restrict__ src, __nv_bfloat16* __restrict__ hi,
                      __nv_bfloat16* __restrict__ lo, int n) {
    int i = blockIdx.x * 256 + threadIdx.x;
    if (i < n) {
        float v = src[i];
        __nv_bfloat16 h = __float2bfloat16(v);
        hi[i] = h;
        lo[i] = __float2bfloat16(v - __bfloat162float(h));
    }
}

// ---------------- one-time weight prep (transpose / concat / gather) ----------------
__global__ void k_prep(const float* __restrict__ W_ih, const float* __restrict__ W_hh,
                       const float* __restrict__ W_dec_att,
                       const float* __restrict__ embedding, const int* __restrict__ caption) {
    int idx = blockIdx.x * blockDim.x + threadIdx.x;
    if (idx < NG_ * KX2_) {
        int j = idx / KX2_, k = idx % KX2_;
        g_Wcat2[idx] = (k < 512) ? W_ih[j * 768 + k] : W_hh[j * 256 + (k - 512)];
    }
    int i2 = idx - NG_ * KX2_;
    if (i2 >= 0 && i2 < ATT_ * DEC_) {
        int k = i2 >> 8, j = i2 & 255;
        g_WdaT[i2] = W_dec_att[j * 256 + k];
    }
    int i3 = i2 - ATT_ * DEC_;
    if (i3 >= 0 && i3 < NG_ * EMB_) {
        int j = i3 >> 8, k = i3 & 255;
        g_Wemb[i3] = W_ih[j * 768 + 512 + k];
    }
    int i4 = i3 - NG_ * EMB_;
    if (i4 >= 0 && i4 < T_ * B_ * EMB_) {
        int m = i4 >> 8, k = i4 & 255;
        int b = m & (B_ - 1), t = m >> 6;
        g_embx[i4] = embedding[(size_t)caption[b * T_ + t] * EMB_ + k];
    }
}

// ---------------- init h0/c0 from mean-pooled encoder ----------------
__global__ void k_init(const float* __restrict__ enc,
                       const float* __restrict__ W_init_h, const float* __restrict__ b_init_h,
                       const float* __restrict__ W_init_c, const float* __restrict__ b_init_c) {
    int b = blockIdx.x, tid = threadIdx.x;
    __shared__ float avg[ENC_];
    #pragma unroll
    for (int e0 = 0; e0 < 2; e0++) {
        int e = tid + e0 * 256;
        float s = 0.f;
        for (int p = 0; p < P_; p++) s += enc[((size_t)(b * P_ + p)) * ENC_ + e];
        avg[e] = s * (1.0f / (float)P_);
    }
    __syncthreads();
    float h = b_init_h[tid], c = b_init_c[tid];
    const float* wh = W_init_h + (size_t)tid * ENC_;
    const float* wc = W_init_c + (size_t)tid * ENC_;
    #pragma unroll 8
    for (int k = 0; k < ENC_; k++) { h += avg[k] * wh[k]; c += avg[k] * wc[k]; }
    g_h0[b * DEC_ + tid] = h;
    g_c[0][b * DEC_ + tid] = c;   // c_0 lives in parity buffer 0
}

// ========== bf16 hi/lo split WMMA GEMM (m16n16k16, fp32 acc; ~1e-5 accuracy) ==========
// C[m][n] = sum_k A[m][k]*B[n][k] (+bias) with A=Ah+Al, B=Bh+Bl; acc = AhBh+AhBl+AlBh.
// CTA 128x128, 8 warps (4m x 2n), warp tile 32x64. K-chunk 32, double-buffered,
// register prefetch. Tiles stored row-major [row][40] bf16 (ldm 40, mult of 8).
// PERM=1: row m encodes (t*B + b); store to C[(b*T + t)*V + n].
#define BT_LD 40
#define BT_TILE (128 * BT_LD)                 // elems per tile per stage
#define BGEMM_SMEM (8 * BT_TILE * 2 + 8 * 16 * 20 * 4)   // 81920 + 10240 bytes

template<int PERM>
__global__ __launch_bounds__(256) void bgemm(
        const __nv_bfloat16* __restrict__ Ah, const __nv_bfloat16* __restrict__ Al,
        const __nv_bfloat16* __restrict__ Bh, const __nv_bfloat16* __restrict__ Bl,
        const float* __restrict__ bias, float* __restrict__ C,
        int M, int N, int K) {
    cudaGridDependencySynchronize();   // PDL: wait for producer data before any reads
    extern __shared__ __align__(16) __nv_bfloat16 smb[];
    __nv_bfloat16* sAh = smb;                 // [2][BT_TILE]
    __nv_bfloat16* sAl = smb + 2 * BT_TILE;
    __nv_bfloat16* sBh = smb + 4 * BT_TILE;
    __nv_bfloat16* sBl = smb + 6 * BT_TILE;
    float* epi = (float*)(smb + 8 * BT_TILE); // [8][16][20]

    int tid = threadIdx.x;
    int wid = tid >> 5, lane = tid & 31;
    int wm = wid & 3, wn = wid >> 2;
    int m0 = blockIdx.x * 128, n0 = blockIdx.y * 128;
    int lrow = tid >> 2;           // 0..63
    int lk8 = (tid & 3) * 8;       // 0,8,16,24 (bf16 elems within 32-chunk)

    const __nv_bfloat16* ApH0 = Ah + (size_t)(m0 + lrow) * K + lk8;
    const __nv_bfloat16* ApH1 = Ah + (size_t)(m0 + lrow + 64) * K + lk8;
    const __nv_bfloat16* ApL0 = Al + (size_t)(m0 + lrow) * K + lk8;
    const __nv_bfloat16* ApL1 = Al + (size_t)(m0 + lrow + 64) * K + lk8;
    bool bok0 = (n0 + lrow) < N, bok1 = (n0 + lrow + 64) < N;
    size_t br0 = (size_t)(bok0 ? n0 + lrow : 0) * K + lk8;
    size_t br1 = (size_t)(bok1 ? n0 + lrow + 64 : 0) * K + lk8;
    const uint4 z4 = make_uint4(0u, 0u, 0u, 0u);

    int so0 = lrow * BT_LD + lk8;
    int so1 = (lrow + 64) * BT_LD + lk8;

    // prologue: chunk 0 -> stage 0
    {
        *(uint4*)(sAh + so0) = *(const uint4*)ApH0;
        *(uint4*)(sAh + so1) = *(const uint4*)ApH1;
        *(uint4*)(sAl + so0) = *(const uint4*)ApL0;
        *(uint4*)(sAl + so1) = *(const uint4*)ApL1;
        *(uint4*)(sBh + so0) = bok0 ? *(const uint4*)(Bh + br0) : z4;
        *(uint4*)(sBh + so1) = bok1 ? *(const uint4*)(Bh + br1) : z4;
        *(uint4*)(sBl + so0) = bok0 ? *(const uint4*)(Bl + br0) : z4;
        *(uint4*)(sBl + so1) = bok1 ? *(const uint4*)(Bl + br1) : z4;
    }
    __syncthreads();

    wmma::fragment<wmma::accumulator, 16, 16, 16, float> acc[2][4];
    #pragma unroll
    for (int mi = 0; mi < 2; mi++)
        #pragma unroll
        for (int ni = 0; ni < 4; ni++) wmma::fill_fragment(acc[mi][ni], 0.f);

    int buf = 0;
    for (int k0 = 32; k0 < K; k0 += 32) {
        uint4 rah0 = *(const uint4*)(ApH0 + k0);
        uint4 rah1 = *(const uint4*)(ApH1 + k0);
        uint4 ral0 = *(const uint4*)(ApL0 + k0);
        uint4 ral1 = *(const uint4*)(ApL1 + k0);
        uint4 rbh0 = bok0 ? *(const uint4*)(Bh + br0 + k0) : z4;
        uint4 rbh1 = bok1 ? *(const uint4*)(Bh + br1 + k0) : z4;
        uint4 rbl0 = bok0 ? *(const uint4*)(Bl + br0 + k0) : z4;
        uint4 rbl1 = bok1 ? *(const uint4*)(Bl + br1 + k0) : z4;

        const __nv_bfloat16* bAh = sAh + buf * BT_TILE;
        const __nv_bfloat16* bAl = sAl + buf * BT_TILE;
        const __nv_bfloat16* bBh = sBh + buf * BT_TILE;
        const __nv_bfloat16* bBl = sBl + buf * BT_TILE;
        #pragma unroll
        for (int ks = 0; ks < 2; ks++) {
            wmma::fragment<wmma::matrix_a, 16, 16, 16, __nv_bfloat16, wmma::row_major> ah[2], al[2];
            wmma::fragment<wmma::matrix_b, 16, 16, 16, __nv_bfloat16, wmma::col_major> bh[4], bl[4];
            #pragma unroll
            for (int mi = 0; mi < 2; mi++) {
                wmma::load_matrix_sync(ah[mi], bAh + (wm * 32 + mi * 16) * BT_LD + ks * 16, BT_LD);
                wmma::load_matrix_sync(al[mi], bAl + (wm * 32 + mi * 16) * BT_LD + ks * 16, BT_LD);
            }
            #pragma unroll
            for (int ni = 0; ni < 4; ni++) {
                wmma::load_matrix_sync(bh[ni], bBh + (wn * 64 + ni * 16) * BT_LD + ks * 16, BT_LD);
                wmma::load_matrix_sync(bl[ni], bBl + (wn * 64 + ni * 16) * BT_LD + ks * 16, BT_LD);
            }
            #pragma unroll
            for (int mi = 0; mi < 2; mi++)
                #pragma unroll
                for (int ni = 0; ni < 4; ni++) {
                    wmma::mma_sync(acc[mi][ni], ah[mi], bh[ni], acc[mi][ni]);
                    wmma::mma_sync(acc[mi][ni], ah[mi], bl[ni], acc[mi][ni]);
                    wmma::mma_sync(acc[mi][ni], al[mi], bh[ni], acc[mi][ni]);
                }
        }
        int nb = buf ^ 1;
        *(uint4*)(sAh + nb * BT_TILE + so0) = rah0;
        *(uint4*)(sAh + nb * BT_TILE + so1) = rah1;
        *(uint4*)(sAl + nb * BT_TILE + so0) = ral0;
        *(uint4*)(sAl + nb * BT_TILE + so1) = ral1;
        *(uint4*)(sBh + nb * BT_TILE + so0) = rbh0;
        *(uint4*)(sBh + nb * BT_TILE + so1) = rbh1;
        *(uint4*)(sBl + nb * BT_TILE + so0) = rbl0;
        *(uint4*)(sBl + nb * BT_TILE + so1) = rbl1;
        __syncthreads();
        buf = nb;
    }
    {
        const __nv_bfloat16* bAh = sAh + buf * BT_TILE;
        const __nv_bfloat16* bAl = sAl + buf * BT_TILE;
        const __nv_bfloat16* bBh = sBh + buf * BT_TILE;
        const __nv_bfloat16* bBl = sBl + buf * BT_TILE;
        #pragma unroll
        for (int ks = 0; ks < 2; ks++) {
            wmma::fragment<wmma::matrix_a, 16, 16, 16, __nv_bfloat16, wmma::row_major> ah[2], al[2];
            wmma::fragment<wmma::matrix_b, 16, 16, 16, __nv_bfloat16, wmma::col_major> bh[4], bl[4];
            #pragma unroll
            for (int mi = 0; mi < 2; mi++) {
                wmma::load_matrix_sync(ah[mi], bAh + (wm * 32 + mi * 16) * BT_LD + ks * 16, BT_LD);
                wmma::load_matrix_sync(al[mi], bAl + (wm * 32 + mi * 16) * BT_LD + ks * 16, BT_LD);
            }
            #pragma unroll
            for (int ni = 0; ni < 4; ni++) {
                wmma::load_matrix_sync(bh[ni], bBh + (wn * 64 + ni * 16) * BT_LD + ks * 16, BT_LD);
                wmma::load_matrix_sync(bl[ni], bBl + (wn * 64 + ni * 16) * BT_LD + ks * 16, BT_LD);
            }
            #pragma unroll
            for (int mi = 0; mi < 2; mi++)
                #pragma unroll
                for (int ni = 0; ni < 4; ni++) {
                    wmma::mma_sync(acc[mi][ni], ah[mi], bh[ni], acc[mi][ni]);
                    wmma::mma_sync(acc[mi][ni], ah[mi], bl[ni], acc[mi][ni]);
                    wmma::mma_sync(acc[mi][ni], al[mi], bh[ni], acc[mi][ni]);
                }
        }
    }

    float* myepi = epi + wid * 16 * 20;
    #pragma unroll
    for (int mi = 0; mi < 2; mi++) {
        #pragma unroll
        for (int ni = 0; ni < 4; ni++) {
            wmma::store_matrix_sync(myepi, acc[mi][ni], 20, wmma::mem_row_major);
            __syncwarp();
            int mbase = m0 + wm * 32 + mi * 16;
            int nbase = n0 + wn * 64 + ni * 16;
            int r = lane >> 1, c0 = (lane & 1) * 8;
            int m = mbase + r;
            size_t rowbase;
            if (PERM) {
                int b = m & (B_ - 1), t = m >> 6;
                rowbase = ((size_t)b * T_ + t) * (size_t)V_;
            } else {
                rowbase = (size_t)m * (size_t)N;
            }
            #pragma unroll
            for (int c = 0; c < 8; c++) {
                int n = nbase + c0 + c;
                if (n < N)
                    C[rowbase + n] = myepi[r * 20 + c0 + c] + (bias ? bias[n] : 0.f);
            }
            __syncwarp();
        }
    }
}

// ---------------- cell body: finishes step (t-1)'s LSTM cell ---------------------------
// Writes h directly as bf16 hi/lo (only the logits GEMM consumes hall).
__device__ __forceinline__ void cell_body(int t, int b, int tid,
                                          const float* __restrict__ b_ih,
                                          const float* __restrict__ b_hh,
                                          float* h_sh) {
    const float* ge = g_gemb + ((size_t)(t - 1) * B_ + b) * NG_;
    float gi = b_ih[tid]       + b_hh[tid]       + ge[tid];
    float gf = b_ih[tid + 256] + b_hh[tid + 256] + ge[tid + 256];
    float gg = b_ih[tid + 512] + b_hh[tid + 512] + ge[tid + 512];
    float go = b_ih[tid + 768] + b_hh[tid + 768] + ge[tid + 768];
    #pragma unroll
    for (int s = 0; s < SPLITK_; s++) {
        const float* gp = g_gpart + ((size_t)s * B_ + b) * NG_;
        gi += gp[tid]; gf += gp[tid + 256]; gg += gp[tid + 512]; go += gp[tid + 768];
    }
    float c  = g_c[(t - 1) & 1][b * DEC_ + tid];
    float cn = sigm(gf) * c + sigm(gi) * tanhf(gg);
    float hn = sigm(go) * tanhf(cn);
    g_c[t & 1][b * DEC_ + tid] = cn;
    size_t hidx = ((size_t)(t - 1) * B_ + b) * DEC_ + tid;
    __nv_bfloat16 hh = __float2bfloat16(hn);
    g_hallH[hidx] = hh;
    g_hallL[hidx] = __float2bfloat16(hn - __bfloat162float(hh));
    if (h_sh) h_sh[tid] = hn;
}

// ---------------- per-step kernel 1: (redundant) cell + att2, then 28 scores ----------
__global__ void k_scores_cell(int t, const float* __restrict__ Wfull,
                              const float* __restrict__ b_ih, const float* __restrict__ b_hh) {
    cudaGridDependencySynchronize();   // PDL: producer (k_gates / prep) data visible
    int b = blockIdx.x, tid = threadIdx.x;
    int p0 = blockIdx.y * 28;
    __shared__ float h_sh[256], att2s[256], wfs[256];

    if (t > 0) cell_body(t, b, tid, b_ih, b_hh, h_sh);
    else       h_sh[tid] = g_h0[b * DEC_ + tid];
    if (blockIdx.y == 0) g_x[b * KX2_ + ENC_ + tid] = h_sh[tid];
    wfs[tid] = Wfull[tid];
    __syncthreads();

    float a2 = 0.f;
    #pragma unroll 8
    for (int k = 0; k < 256; k++) a2 += h_sh[k] * g_WdaT[k * 256 + tid];
    att2s[tid] = a2;
    __syncthreads();

    int lane = tid & 31, wid = tid >> 5;
    for (int p = p0 + wid; p < p0 + 28; p += 8) {
        const float* row = g_att1 + ((size_t)(b * P_ + p)) * ATT_;
        float s = 0.f;
        #pragma unroll
        for (int a = lane; a < 256; a += 32) {
            float v = row[a] + att2s[a];
            s += fmaxf(v, 0.f) * wfs[a];
        }
        #pragma unroll
        for (int o = 16; o > 0; o >>= 1) s += __shfl_down_sync(0xffffffffu, s, o);
        if (lane == 0) g_scores[b * P_ + p] = s;
    }
}

// ---------------- final cell only (after last step's gates) ----------------------------
__global__ void k_cell_final(const float* __restrict__ b_ih, const float* __restrict__ b_hh) {
    cudaGridDependencySynchronize();
    cell_body(T_, blockIdx.x, threadIdx.x, b_ih, b_hh, nullptr);
}

// ---------------- per-step kernel 2: softmax (recomputed per block) + 64-e ctx chunk ---
__global__ void k_softmax_ctx(int t, const float* __restrict__ enc,
                              float* __restrict__ alphas_out) {
    cudaGridDependencySynchronize();   // PDL: g_scores from k_scores_cell visible
    int b = blockIdx.x, tid = threadIdx.x;
    int e0 = blockIdx.y * 64;
    __shared__ float sc[256], red[256];
    float sv = (tid < P_) ? g_scores[b * P_ + tid] : -1e30f;
    red[tid] = sv;
    __syncthreads();
    for (int s = 128; s > 0; s >>= 1) { if (tid < s) red[tid] = fmaxf(red[tid], red[tid + s]); __syncthreads(); }
    float mx = red[0];
    __syncthreads();
    float ex = (tid < P_) ? expf(sv - mx) : 0.f;
    red[tid] = ex;
    __syncthreads();
    for (int s = 128; s > 0; s >>= 1) { if (tid < s) red[tid] += red[tid + s]; __syncthreads(); }
    float inv = 1.0f / red[0];
    float alpha = ex * inv;
    sc[tid] = alpha;
    if (blockIdx.y == 0 && tid < P_)
        alphas_out[((size_t)b * T_ + t) * P_ + tid] = alpha;
    __syncthreads();
    int e = tid & 63, ps = tid >> 6;
    float s = 0.f;
    for (int p = ps; p < P_; p += 4)
        s += sc[p] * enc[((size_t)(b * P_ + p)) * ENC_ + e0 + e];
    red[tid] = s;
    __syncthreads();
    if (tid < 64)
        g_x[b * KX2_ + e0 + tid] = red[tid] + red[tid + 64] + red[tid + 128] + red[tid + 192];
}

// ---------------- per-step kernel 3: gates GEMM, split-K over K=768 (12 x 64) ----------
__global__ void k_gates() {
    cudaGridDependencySynchronize();   // PDL: g_x from k_softmax_ctx visible
    __shared__ float Xs[64][68];
    __shared__ float Ws[64][68];
    int tid = threadIdx.x;
    int j0 = blockIdx.x * 64;
    int k0 = blockIdx.y * 64;
    #pragma unroll
    for (int r = 0; r < 16; r++) {
        int row = r * 4 + (tid >> 6);
        int k = tid & 63;
        Xs[k][row] = g_x[(size_t)row * KX2_ + k0 + k];
        Ws[k][row] = g_Wcat2[(size_t)(j0 + row) * KX2_ + k0 + k];
    }
    __syncthreads();
    int tx = tid & 15, ty = tid >> 4;
    float acc[4][4] = {};
    #pragma unroll
    for (int kk = 0; kk < 64; kk++) {
        float4 xb = *(const float4*)&Xs[kk][ty * 4];
        float4 wj = *(const float4*)&Ws[kk][tx * 4];
        acc[0][0] += xb.x * wj.x; acc[0][1] += xb.x * wj.y; acc[0][2] += xb.x * wj.z; acc[0][3] += xb.x * wj.w;
        acc[1][0] += xb.y * wj.x; acc[1][1] += xb.y * wj.y; acc[1][2] += xb.y * wj.z; acc[1][3] += xb.y * wj.w;
        acc[2][0] += xb.z * wj.x; acc[2][1] += xb.z * wj.y; acc[2][2] += xb.z * wj.z; acc[2][3] += xb.z * wj.w;
        acc[3][0] += xb.w * wj.x; acc[3][1] += xb.w * wj.y; acc[3][2] += xb.w * wj.z; acc[3][3] += xb.w * wj.w;
    }
    #pragma unroll
    for (int bi = 0; bi < 4; bi++) {
        int b = ty * 4 + bi;
        #pragma unroll
        for (int ji = 0; ji < 4; ji++) {
            g_gpart[((size_t)blockIdx.y * B_ + b) * NG_ + j0 + tx * 4 + ji] = acc[bi][ji];
        }
    }
}

// ---------------- launch ----------------
extern "C" void kernel_launch(void* const* d_in, const int* in_sizes, int n_in,
                              void* d_out, int out_size) {
    const float* enc       = (const float*)d_in[0];
    const int*   caption   = (const int*)  d_in[1];
    const float* W_enc_att = (const float*)d_in[2];
    const float* W_dec_att = (const float*)d_in[3];
    const float* W_full    = (const float*)d_in[4];
    const float* embedding = (const float*)d_in[5];
    const float* W_init_h  = (const float*)d_in[6];
    const float* b_init_h  = (const float*)d_in[7];
    const float* W_init_c  = (const float*)d_in[8];
    const float* b_init_c  = (const float*)d_in[9];
    const float* W_ih      = (const float*)d_in[10];
    const float* b_ih      = (const float*)d_in[11];
    const float* W_hh      = (const float*)d_in[12];
    const float* b_hh      = (const float*)d_in[13];
    const float* W_out     = (const float*)d_in[14];
    const float* b_out     = (const float*)d_in[15];

    float* out    = (float*)d_out;
    float* preds  = out;                              // [B, T, V]
    float* alphas = out + (size_t)B_ * T_ * V_;       // [B, T, P]

    float *att1p, *embxp, *wembp, *gembp;
    cudaGetSymbolAddress((void**)&att1p, g_att1);
    cudaGetSymbolAddress((void**)&embxp, g_embx);
    cudaGetSymbolAddress((void**)&wembp, g_Wemb);
    cudaGetSymbolAddress((void**)&gembp, g_gemb);

    __nv_bfloat16 *encH, *encL, *weaH, *weaL, *embxH, *embxL, *wembH, *wembL,
                  *hallH, *hallL, *woutH, *woutL;
    cudaGetSymbolAddress((void**)&encH, g_encH);   cudaGetSymbolAddress((void**)&encL, g_encL);
    cudaGetSymbolAddress((void**)&weaH, g_weaH);   cudaGetSymbolAddress((void**)&weaL, g_weaL);
    cudaGetSymbolAddress((void**)&embxH, g_embxH); cudaGetSymbolAddress((void**)&embxL, g_embxL);
    cudaGetSymbolAddress((void**)&wembH, g_wembH); cudaGetSymbolAddress((void**)&wembL, g_wembL);
    cudaGetSymbolAddress((void**)&hallH, g_hallH); cudaGetSymbolAddress((void**)&hallL, g_hallL);
    cudaGetSymbolAddress((void**)&woutH, g_woutH); cudaGetSymbolAddress((void**)&woutL, g_woutL);

    cudaFuncSetAttribute(bgemm<0>, cudaFuncAttributeMaxDynamicSharedMemorySize, BGEMM_SMEM);
    cudaFuncSetAttribute(bgemm<1>, cudaFuncAttributeMaxDynamicSharedMemorySize, BGEMM_SMEM);

    // PDL launch configs for the recurrence kernels
    cudaLaunchAttribute pdl;
    pdl.id = cudaLaunchAttributeProgrammaticStreamSerialization;
    pdl.val.programmaticStreamSerializationAllowed = 1;
    cudaLaunchConfig_t cfg_sc = {};   // k_scores_cell
    cfg_sc.gridDim = dim3(B_, 7); cfg_sc.blockDim = dim3(256);
    cfg_sc.attrs = &pdl; cfg_sc.numAttrs = 1;
    cudaLaunchConfig_t cfg_sm = {};   // k_softmax_ctx
    cfg_sm.gridDim = dim3(B_, 8); cfg_sm.blockDim = dim3(256);
    cfg_sm.attrs = &pdl; cfg_sm.numAttrs = 1;
    cudaLaunchConfig_t cfg_ga = {};   // k_gates
    cfg_ga.gridDim = dim3(NG_ / 64, SPLITK_); cfg_ga.blockDim = dim3(256);
    cfg_ga.attrs = &pdl; cfg_ga.numAttrs = 1;
    cudaLaunchConfig_t cfg_cf = {};   // k_cell_final
    cfg_cf.gridDim = dim3(B_); cfg_cf.blockDim = dim3(256);
    cfg_cf.attrs = &pdl; cfg_cf.numAttrs = 1;
    cudaLaunchConfig_t cfg_lg = {};   // logits bgemm
    cfg_lg.gridDim = dim3((T_ * B_) / 128, (V_ + 127) / 128); cfg_lg.blockDim = dim3(256);
    cfg_lg.dynamicSmemBytes = BGEMM_SMEM;
    cfg_lg.attrs = &pdl; cfg_lg.numAttrs = 1;

    // one-time prep
    int prep_total = NG_ * KX2_ + ATT_ * DEC_ + NG_ * EMB_ + T_ * B_ * EMB_;
    k_prep<<<(prep_total + 255) / 256, 256>>>(W_ih, W_hh, W_dec_att, embedding, caption);
    k_init<<<B_, 256>>>(enc, W_init_h, b_init_h, W_init_c, b_init_c);

    // bf16 hi/lo conversions for tensor GEMM operands
    k_cvt<<<(B_ * P_ * ENC_ + 255) / 256, 256>>>(enc, encH, encL, B_ * P_ * ENC_);
    k_cvt<<<(ATT_ * ENC_ + 255) / 256, 256>>>(W_enc_att, weaH, weaL, ATT_ * ENC_);
    k_cvt<<<(T_ * B_ * EMB_ + 255) / 256, 256>>>(embxp, embxH, embxL, T_ * B_ * EMB_);
    k_cvt<<<(NG_ * EMB_ + 255) / 256, 256>>>(wembp, wembH, wembL, NG_ * EMB_);
    k_cvt<<<(V_ * DEC_ + 255) / 256, 256>>>(W_out, woutH, woutL, V_ * DEC_);

    // att1[b,p,a] = enc[b,p,:] . W_enc_att[a,:]   (M=12544, N=256, K=512)  tensor
    bgemm<0><<<dim3(98, 2), 256, BGEMM_SMEM>>>(encH, encL, weaH, weaL, nullptr, att1p,
                                               B_ * P_, ATT_, ENC_);
    // gemb[t*B+b][j] = embx . Wemb^T               (M=2816, N=1024, K=256)  tensor
    bgemm<0><<<dim3(22, 8), 256, BGEMM_SMEM>>>(embxH, embxL, wembH, wembL, nullptr, gembp,
                                               T_ * B_, NG_, EMB_);

    // recurrence: 3 wide kernels per step, launched with PDL to hide launch latency
    for (int t = 0; t < T_; t++) {
        cudaLaunchKernelEx(&cfg_sc, k_scores_cell, t, W_full, b_ih, b_hh);
        cudaLaunchKernelEx(&cfg_sm, k_softmax_ctx, t, enc, (float*)alphas);
        cudaLaunchKernelEx(&cfg_ga, k_gates);
    }
    cudaLaunchKernelEx(&cfg_cf, k_cell_final, b_ih, b_hh);

    // batched logits (hall already bf16 hi/lo from the cell): -> [B, T, V]
    cudaLaunchKernelEx(&cfg_lg, bgemm<1>,
                       (const __nv_bfloat16*)hallH, (const __nv_bfloat16*)hallL,
                       (const __nv_bfloat16*)woutH, (const __nv_bfloat16*)woutL,
                       (const float*)b_out, (float*)preds, T_ * B_, V_, DEC_);
}